// round 2
// baseline (speedup 1.0000x reference)
#include <cuda_runtime.h>

// out[t, :] = W[seq[t], :] + W[pre[t], :] + W[post[t], :]
// D = 128 floats per row. One warp per token; lane l handles float4 #l (16B),
// 32 lanes * 16B = 512B = full row. Gather rows are 4 consecutive 128B
// sectors -> fully coalesced. Weight table (51.2 MB) fits in L2.

#define EMBED_VEC 32          // 128 floats / 4 per float4
#define THREADS_PER_BLOCK 256
#define WARPS_PER_BLOCK (THREADS_PER_BLOCK / 32)

__global__ __launch_bounds__(THREADS_PER_BLOCK)
void cbow_subword_kernel(const int* __restrict__ seq,
                         const int* __restrict__ pre,
                         const int* __restrict__ post,
                         const float4* __restrict__ W,   // [VOCAB, 32] float4
                         float4* __restrict__ out,       // [n_tok, 32] float4
                         int n_tok) {
    int warp = (blockIdx.x * WARPS_PER_BLOCK) + (threadIdx.x >> 5);
    int lane = threadIdx.x & 31;
    if (warp >= n_tok) return;

    // Scalar index loads; all lanes read the same address -> L1 broadcast.
    int i0 = __ldg(seq + warp);
    int i1 = __ldg(pre + warp);
    int i2 = __ldg(post + warp);

    // Three independent row-segment loads (MLP=3 per thread).
    float4 a = __ldg(W + (size_t)i0 * EMBED_VEC + lane);
    float4 b = __ldg(W + (size_t)i1 * EMBED_VEC + lane);
    float4 c = __ldg(W + (size_t)i2 * EMBED_VEC + lane);

    float4 r;
    r.x = a.x + b.x + c.x;
    r.y = a.y + b.y + c.y;
    r.z = a.z + b.z + c.z;
    r.w = a.w + b.w + c.w;

    out[(size_t)warp * EMBED_VEC + lane] = r;
}

extern "C" void kernel_launch(void* const* d_in, const int* in_sizes, int n_in,
                              void* d_out, int out_size) {
    // metadata order: sequence [B,S] i32, prefix_idx [B,S] i32,
    //                 postfix_idx [B,S] i32, weight [VOCAB,128] f32
    const int*    seq  = (const int*)d_in[0];
    const int*    pre  = (const int*)d_in[1];
    const int*    post = (const int*)d_in[2];
    const float4* W    = (const float4*)d_in[3];
    float4*       out  = (float4*)d_out;

    int n_tok = in_sizes[0];             // 128 * 1024 = 131072
    int blocks = (n_tok + WARPS_PER_BLOCK - 1) / WARPS_PER_BLOCK;

    cbow_subword_kernel<<<blocks, THREADS_PER_BLOCK>>>(seq, pre, post, W, out, n_tok);
}

// round 3
// speedup vs baseline: 1.2764x; 1.2764x over previous
#include <cuda_runtime.h>

// out[t, :] = W[seq[t], :] + W[pre[t], :] + W[post[t], :]
// D = 128 floats. One warp covers a 512B row (lane l -> float4 #l).
// Latency-bound fix: 4 tokens per warp, all 12 gather loads issued
// back-to-back (MLP=12/thread) before any arithmetic/store.

#define EMBED_VEC 32
#define THREADS_PER_BLOCK 256
#define WARPS_PER_BLOCK (THREADS_PER_BLOCK / 32)
#define TPW 4   // tokens per warp

__global__ __launch_bounds__(THREADS_PER_BLOCK)
void cbow_subword_kernel(const int* __restrict__ seq,
                         const int* __restrict__ pre,
                         const int* __restrict__ post,
                         const float4* __restrict__ W,
                         float4* __restrict__ out,
                         int n_tok) {
    int warp = blockIdx.x * WARPS_PER_BLOCK + (threadIdx.x >> 5);
    int lane = threadIdx.x & 31;
    int t0 = warp * TPW;
    if (t0 >= n_tok) return;

    if (t0 + TPW <= n_tok) {
        // Batch all index loads (uniform per warp -> broadcast).
        int ia[TPW], ib[TPW], ic[TPW];
        #pragma unroll
        for (int j = 0; j < TPW; j++) {
            ia[j] = __ldg(seq  + t0 + j);
            ib[j] = __ldg(pre  + t0 + j);
            ic[j] = __ldg(post + t0 + j);
        }
        // Batch all 12 row-segment gathers: maximal MLP before first use.
        float4 va[TPW], vb[TPW], vc[TPW];
        #pragma unroll
        for (int j = 0; j < TPW; j++) va[j] = __ldg(W + (size_t)ia[j] * EMBED_VEC + lane);
        #pragma unroll
        for (int j = 0; j < TPW; j++) vb[j] = __ldg(W + (size_t)ib[j] * EMBED_VEC + lane);
        #pragma unroll
        for (int j = 0; j < TPW; j++) vc[j] = __ldg(W + (size_t)ic[j] * EMBED_VEC + lane);

        #pragma unroll
        for (int j = 0; j < TPW; j++) {
            float4 r;
            r.x = va[j].x + vb[j].x + vc[j].x;
            r.y = va[j].y + vb[j].y + vc[j].y;
            r.z = va[j].z + vb[j].z + vc[j].z;
            r.w = va[j].w + vb[j].w + vc[j].w;
            // Streaming store: don't let the 67MB output evict the
            // 51MB weight table from L2.
            __stcs(out + (size_t)(t0 + j) * EMBED_VEC + lane, r);
        }
    } else {
        // Tail (not hit for 131072 tokens, kept for generality).
        for (int t = t0; t < n_tok; t++) {
            int i0 = __ldg(seq + t), i1 = __ldg(pre + t), i2 = __ldg(post + t);
            float4 a = __ldg(W + (size_t)i0 * EMBED_VEC + lane);
            float4 b = __ldg(W + (size_t)i1 * EMBED_VEC + lane);
            float4 c = __ldg(W + (size_t)i2 * EMBED_VEC + lane);
            float4 r;
            r.x = a.x + b.x + c.x;
            r.y = a.y + b.y + c.y;
            r.z = a.z + b.z + c.z;
            r.w = a.w + b.w + c.w;
            __stcs(out + (size_t)t * EMBED_VEC + lane, r);
        }
    }
}

extern "C" void kernel_launch(void* const* d_in, const int* in_sizes, int n_in,
                              void* d_out, int out_size) {
    const int*    seq  = (const int*)d_in[0];
    const int*    pre  = (const int*)d_in[1];
    const int*    post = (const int*)d_in[2];
    const float4* W    = (const float4*)d_in[3];
    float4*       out  = (float4*)d_out;

    int n_tok = in_sizes[0];  // 131072
    int tokens_per_block = WARPS_PER_BLOCK * TPW;
    int blocks = (n_tok + tokens_per_block - 1) / tokens_per_block;

    cbow_subword_kernel<<<blocks, THREADS_PER_BLOCK>>>(seq, pre, post, W, out, n_tok);
}